// round 10
// baseline (speedup 1.0000x reference)
#include <cuda_runtime.h>
#include <cuda_fp16.h>
#include <cstdint>

#define N_MAX 100000
#define E_MAX 3200000

#define G1_NODES 256
#define G1_TK 32
#define G1_PAD 36

// ---------------- scratch (static device globals; no allocs) ----------------
__device__ int    d_is64;
__device__ int    d_deg[N_MAX];
__device__ int    d_row[N_MAX + 1];
__device__ int    d_pos[N_MAX];
__device__ int    d_bsum[256];
__device__ int    d_srcs[E_MAX];
__device__ float  d_dis[N_MAX];
__device__ float  d_g1[(size_t)N_MAX * 16];      // fp32 gemm1 output (unscaled)
__device__ __half d_g1h[(size_t)N_MAX * 16];     // fp16 scaled layer-1 features
__device__ __half d_g2h[(size_t)N_MAX * 16];     // fp16 scaled layer-2 features

// ---------------- init: zero degrees; block 0 also probes edge dtype ----------------
__global__ void k_init(const int* __restrict__ ei32, int e, int n) {
    int i = blockIdx.x * blockDim.x + threadIdx.x;
    if (i < n) d_deg[i] = 0;
    if (blockIdx.x == 0) {
        int total32 = 2 * e;               // in-bounds under BOTH interpretations
        int stride = (total32 / 2048) * 2; // even stride keeps parity odd
        if (stride < 2) stride = 2;
        int nz = 0;
#pragma unroll
        for (int r = 0; r < 4; r++) {
            long long p = 1 + (long long)(threadIdx.x * 4 + r) * stride;
            if (p < total32) nz += (__ldg(&ei32[p]) != 0);
        }
        int any = __syncthreads_or(nz);
        if (threadIdx.x == 0) d_is64 = any ? 0 : 1;
    }
}

// ---------------- count: 2 edges/thread, vectorized dst loads ----------------
__global__ void k_count(const void* __restrict__ ei, int e, int n) {
    int i2 = (blockIdx.x * blockDim.x + threadIdx.x) * 2;
    if (i2 >= e) return;
    int is64 = d_is64;
    int d0, d1 = -1;
    bool two = (i2 + 1 < e);
    if (is64) {
        const long long* p = (const long long*)ei + e + i2;   // dst row
        if (two) {
            longlong2 v = *(const longlong2*)p;
            d0 = (int)v.x; d1 = (int)v.y;
        } else d0 = (int)p[0];
    } else {
        const int* p = (const int*)ei + e + i2;
        if (two) {
            int2 v = *(const int2*)p;
            d0 = v.x; d1 = v.y;
        } else d0 = p[0];
    }
    if (d0 >= 0 && d0 < n) atomicAdd(&d_deg[d0], 1);
    if (two && d1 >= 0 && d1 < n) atomicAdd(&d_deg[d1], 1);
}

// block-wise exclusive scan of deg into row (warp-shuffle), block totals into bsum
__global__ void k_scan_block(int n) {
    __shared__ int wsum[32];
    int lane = threadIdx.x & 31, wid = threadIdx.x >> 5;
    int i = blockIdx.x * 1024 + threadIdx.x;
    int v = (i < n) ? d_deg[i] : 0;
    int incl = v;
#pragma unroll
    for (int off = 1; off < 32; off <<= 1) {
        int t = __shfl_up_sync(0xffffffffu, incl, off);
        if (lane >= off) incl += t;
    }
    if (lane == 31) wsum[wid] = incl;
    __syncthreads();
    if (wid == 0) {
        int w = wsum[lane];
#pragma unroll
        for (int off = 1; off < 32; off <<= 1) {
            int t = __shfl_up_sync(0xffffffffu, w, off);
            if (lane >= off) w += t;
        }
        wsum[lane] = w;
    }
    __syncthreads();
    int add = wid ? wsum[wid - 1] : 0;
    incl += add;
    if (i < n) d_row[i] = incl - v;              // exclusive within block
    if (threadIdx.x == 1023) d_bsum[blockIdx.x] = incl;
}

// add block-prefix (single-warp shfl reduction per block), build pos/dis
__global__ void k_scan_add(int n, int nb) {
    __shared__ int sS, sT;
    int tid = threadIdx.x;
    int i = blockIdx.x * 256 + tid;
    int seg = blockIdx.x >> 2;                   // this block's 1024-wide segment
    if (tid < 32) {
        int s_lt = 0, s_all = 0;
        for (int j = tid; j < nb; j += 32) {
            int b = d_bsum[j];
            s_all += b;
            if (j < seg) s_lt += b;
        }
#pragma unroll
        for (int off = 16; off >= 1; off >>= 1) {
            s_lt  += __shfl_xor_sync(0xffffffffu, s_lt, off);
            s_all += __shfl_xor_sync(0xffffffffu, s_all, off);
        }
        if (tid == 0) { sS = s_lt; sT = s_all; }
    }
    __syncthreads();
    int S = sS, total = sT;
    if (i < n) {
        int r = d_row[i] + S;
        d_row[i] = r;
        d_pos[i] = r;
        d_dis[i] = rsqrtf((float)(d_deg[i] + 1));   // +1 = self loop
    }
    if (i == 0) d_row[n] = total;
}

// ---------------- place: 2 edges/thread, vectorized src/dst loads ----------------
__global__ void k_place(const void* __restrict__ ei, int e, int n) {
    int i2 = (blockIdx.x * blockDim.x + threadIdx.x) * 2;
    if (i2 >= e) return;
    int is64 = d_is64;
    int s0, d0, s1 = -1, d1 = -1;
    bool two = (i2 + 1 < e);
    if (is64) {
        const long long* ps = (const long long*)ei + i2;
        const long long* pd = (const long long*)ei + e + i2;
        if (two) {
            longlong2 vs = *(const longlong2*)ps;
            longlong2 vd = *(const longlong2*)pd;
            s0 = (int)vs.x; s1 = (int)vs.y;
            d0 = (int)vd.x; d1 = (int)vd.y;
        } else { s0 = (int)ps[0]; d0 = (int)pd[0]; }
    } else {
        const int* ps = (const int*)ei + i2;
        const int* pd = (const int*)ei + e + i2;
        if (two) {
            int2 vs = *(const int2*)ps;
            int2 vd = *(const int2*)pd;
            s0 = vs.x; s1 = vs.y;
            d0 = vd.x; d1 = vd.y;
        } else { s0 = ps[0]; d0 = pd[0]; }
    }
    if (d0 >= 0 && d0 < n && s0 >= 0 && s0 < n) {
        int p = atomicAdd(&d_pos[d0], 1);
        if (p >= 0 && p < E_MAX) d_srcs[p] = s0;
    }
    if (two && d1 >= 0 && d1 < n && s1 >= 0 && s1 < n) {
        int p = atomicAdd(&d_pos[d1], 1);
        if (p >= 0 && p < E_MAX) d_srcs[p] = s1;
    }
}

// ---------------- layer-1 GEMM: g1 = x @ w1 (UNscaled; dis+half convert later) ----------------
__global__ void __launch_bounds__(128) k_gemm1(const float* __restrict__ x,
                                               const float* __restrict__ w1, int n) {
    __shared__ float xs[G1_NODES][G1_PAD];
    __shared__ float ws[G1_TK * 16];
    int tid = threadIdx.x;
    int base = blockIdx.x * G1_NODES;

    unsigned long long a0[8], a1[8];
#pragma unroll
    for (int q = 0; q < 8; q++) { a0[q] = 0ull; a1[q] = 0ull; }

    for (int kt = 0; kt < 512; kt += G1_TK) {
        ((float4*)ws)[tid] = ((const float4*)(w1 + (size_t)kt * 16))[tid];
#pragma unroll
        for (int r = 0; r < 16; r++) {
            int f4 = r * 128 + tid;
            int rown = f4 >> 3;
            int col  = f4 & 7;
            int gn = base + rown;
            float4 v = make_float4(0.f, 0.f, 0.f, 0.f);
            if (gn < n) v = *(const float4*)&x[(size_t)gn * 512 + kt + col * 4];
            *(float4*)&xs[rown][col * 4] = v;
        }
        __syncthreads();
#pragma unroll
        for (int k4 = 0; k4 < G1_TK / 4; k4++) {
            float4 xa = *(const float4*)&xs[tid][k4 * 4];
            float4 xb = *(const float4*)&xs[tid + 128][k4 * 4];
#pragma unroll
            for (int kk = 0; kk < 4; kk++) {
                int k = k4 * 4 + kk;
                const ulonglong2* wp2 = (const ulonglong2*)&ws[k * 16];
                float fa = (&xa.x)[kk];
                float fb = (&xb.x)[kk];
                unsigned long long pa, pb;
                asm("mov.b64 %0, {%1, %1};" : "=l"(pa) : "f"(fa));
                asm("mov.b64 %0, {%1, %1};" : "=l"(pb) : "f"(fb));
#pragma unroll
                for (int q = 0; q < 4; q++) {
                    ulonglong2 w2v = wp2[q];
                    asm("fma.rn.f32x2 %0, %1, %2, %0;" : "+l"(a0[2 * q])     : "l"(pa), "l"(w2v.x));
                    asm("fma.rn.f32x2 %0, %1, %2, %0;" : "+l"(a0[2 * q + 1]) : "l"(pa), "l"(w2v.y));
                    asm("fma.rn.f32x2 %0, %1, %2, %0;" : "+l"(a1[2 * q])     : "l"(pb), "l"(w2v.x));
                    asm("fma.rn.f32x2 %0, %1, %2, %0;" : "+l"(a1[2 * q + 1]) : "l"(pb), "l"(w2v.y));
                }
            }
        }
        __syncthreads();
    }

#pragma unroll
    for (int half = 0; half < 2; half++) {
        int node = base + half * 128 + tid;
        if (node < n) {
            unsigned long long* ap = half ? a1 : a0;
            float outv[16];
#pragma unroll
            for (int q = 0; q < 8; q++) {
                float lo, hi;
                asm("mov.b64 {%0, %1}, %2;" : "=f"(lo), "=f"(hi) : "l"(ap[q]));
                outv[2 * q]     = lo;
                outv[2 * q + 1] = hi;
            }
#pragma unroll
            for (int q = 0; q < 4; q++)
                *(float4*)&d_g1[(size_t)node * 16 + q * 4] =
                    make_float4(outv[4 * q], outv[4 * q + 1], outv[4 * q + 2], outv[4 * q + 3]);
        }
    }
}

// ---------------- scale + convert: g1h = half(g1 * dis[node]) ----------------
__global__ void k_scale(int n) {
    int t = blockIdx.x * blockDim.x + threadIdx.x;   // one float4 -> 4 halves per thread
    int node = t >> 2;
    if (node < n) {
        float di = __ldg(&d_dis[node]);
        float4 v = *(const float4*)&d_g1[(size_t)t * 4];
        __half2 h01 = __floats2half2_rn(v.x * di, v.y * di);
        __half2 h23 = __floats2half2_rn(v.z * di, v.w * di);
        uint2 st;
        st.x = *(unsigned int*)&h01;
        st.y = *(unsigned int*)&h23;
        *(uint2*)&d_g1h[(size_t)t * 4] = st;
    }
}

// 8-deep batched gather accumulate over a strided edge range (stride 2)
__device__ __forceinline__ void gather_range(const __half* __restrict__ tab,
                                             int rs, int re, int c,
                                             float& ax, float& ay, float& az, float& aw) {
    int e2 = rs;
    int last8 = re - 15;                    // room for offsets e2..e2+14
    for (; e2 < last8; e2 += 16) {
        int idx[8];
#pragma unroll
        for (int j = 0; j < 8; j++) idx[j] = __ldg(&d_srcs[e2 + 2 * j]);
        uint2 raw[8];
#pragma unroll
        for (int j = 0; j < 8; j++)
            raw[j] = *(const uint2*)&tab[(size_t)idx[j] * 16 + c * 4];
#pragma unroll
        for (int j = 0; j < 8; j++) {
            float2 lo = __half22float2(*(__half2*)&raw[j].x);
            float2 hi = __half22float2(*(__half2*)&raw[j].y);
            ax += lo.x; ay += lo.y; az += hi.x; aw += hi.y;
        }
    }
    for (; e2 < re; e2 += 2) {
        int s = __ldg(&d_srcs[e2]);
        uint2 raw = *(const uint2*)&tab[(size_t)s * 16 + c * 4];
        float2 lo = __half22float2(*(__half2*)&raw.x);
        float2 hi = __half22float2(*(__half2*)&raw.y);
        ax += lo.x; ay += lo.y; az += hi.x; aw += hi.y;
    }
}

// ---------------- gather 1: 8 threads/node, half features, fused GEMM2 ----------------
__global__ void k_gather1(const float* __restrict__ b1,
                          const float* __restrict__ w2, int n) {
    __shared__ float w2s[256];
    if (threadIdx.x < 256) w2s[threadIdx.x] = w2[threadIdx.x];
    __syncthreads();

    int t = blockIdx.x * blockDim.x + threadIdx.x;
    int node = t >> 3, c = t & 3, h = (t >> 2) & 1;
    bool act = node < n;
    int nc = act ? node : (n - 1);

    int rs = __ldg(&d_row[nc]), re = __ldg(&d_row[nc + 1]);
    float di = __ldg(&d_dis[nc]);
    float ax = 0.f, ay = 0.f, az = 0.f, aw = 0.f;
    if (h == 0) {
        uint2 raw = *(const uint2*)&d_g1h[(size_t)nc * 16 + c * 4];
        float2 lo = __half22float2(*(__half2*)&raw.x);
        float2 hi = __half22float2(*(__half2*)&raw.y);
        ax = lo.x; ay = lo.y; az = hi.x; aw = hi.y;
    }
    gather_range(d_g1h, rs + h, re, c, ax, ay, az, aw);
    ax += __shfl_xor_sync(0xffffffffu, ax, 4);
    ay += __shfl_xor_sync(0xffffffffu, ay, 4);
    az += __shfl_xor_sync(0xffffffffu, az, 4);
    aw += __shfl_xor_sync(0xffffffffu, aw, 4);

    float4 b4 = *(const float4*)&b1[c * 4];
    float al[4];
    al[0] = fmaxf(fmaf(ax, di, b4.x), 0.f);
    al[1] = fmaxf(fmaf(ay, di, b4.y), 0.f);
    al[2] = fmaxf(fmaf(az, di, b4.z), 0.f);
    al[3] = fmaxf(fmaf(aw, di, b4.w), 0.f);

    int lane = threadIdx.x & 31;
    int lb = lane & ~3;
    float h2[4] = {0.f, 0.f, 0.f, 0.f};
#pragma unroll
    for (int j = 0; j < 16; j++) {
        float aj = __shfl_sync(0xffffffffu, al[j & 3], lb + (j >> 2));
#pragma unroll
        for (int q = 0; q < 4; q++)
            h2[q] = fmaf(aj, w2s[j * 16 + c * 4 + q], h2[q]);
    }
    if (act && h == 0) {
        __half2 o01 = __floats2half2_rn(h2[0] * di, h2[1] * di);
        __half2 o23 = __floats2half2_rn(h2[2] * di, h2[3] * di);
        uint2 st;
        st.x = *(unsigned int*)&o01;
        st.y = *(unsigned int*)&o23;
        *(uint2*)&d_g2h[(size_t)node * 16 + c * 4] = st;
    }
}

// ---------------- gather 2: 8 threads/node, logits + log_softmax ----------------
__global__ void k_gather2(const float* __restrict__ b2, float* __restrict__ out, int n) {
    int t = blockIdx.x * blockDim.x + threadIdx.x;
    int node = t >> 3, c = t & 3, h = (t >> 2) & 1;
    bool act = node < n;
    int nc = act ? node : (n - 1);

    int rs = __ldg(&d_row[nc]), re = __ldg(&d_row[nc + 1]);
    float di = __ldg(&d_dis[nc]);
    float ax = 0.f, ay = 0.f, az = 0.f, aw = 0.f;
    if (h == 0) {
        uint2 raw = *(const uint2*)&d_g2h[(size_t)nc * 16 + c * 4];
        float2 lo = __half22float2(*(__half2*)&raw.x);
        float2 hi = __half22float2(*(__half2*)&raw.y);
        ax = lo.x; ay = lo.y; az = hi.x; aw = hi.y;
    }
    gather_range(d_g2h, rs + h, re, c, ax, ay, az, aw);
    ax += __shfl_xor_sync(0xffffffffu, ax, 4);
    ay += __shfl_xor_sync(0xffffffffu, ay, 4);
    az += __shfl_xor_sync(0xffffffffu, az, 4);
    aw += __shfl_xor_sync(0xffffffffu, aw, 4);

    float4 b4 = *(const float4*)&b2[c * 4];
    float l0 = fmaf(ax, di, b4.x);
    float l1 = fmaf(ay, di, b4.y);
    float l2 = fmaf(az, di, b4.z);
    float l3 = fmaf(aw, di, b4.w);

    float m = fmaxf(fmaxf(l0, l1), fmaxf(l2, l3));
    m = fmaxf(m, __shfl_xor_sync(0xffffffffu, m, 1));
    m = fmaxf(m, __shfl_xor_sync(0xffffffffu, m, 2));
    float s4 = expf(l0 - m) + expf(l1 - m) + expf(l2 - m) + expf(l3 - m);
    s4 += __shfl_xor_sync(0xffffffffu, s4, 1);
    s4 += __shfl_xor_sync(0xffffffffu, s4, 2);
    float lse = m + logf(s4);

    if (act && h == 0)
        *(float4*)&out[(size_t)node * 16 + c * 4] =
            make_float4(l0 - lse, l1 - lse, l2 - lse, l3 - lse);
}

// ---------------- launch (fork: gemm1+scale parallel with graph preprocessing) ----------------
extern "C" void kernel_launch(void* const* d_in, const int* in_sizes, int n_in,
                              void* d_out, int out_size) {
    static cudaStream_t s2 = nullptr;
    static cudaEvent_t ev_fork = nullptr, ev_scan = nullptr, ev_join = nullptr;
    if (s2 == nullptr) {
        cudaStreamCreateWithFlags(&s2, cudaStreamNonBlocking);
        cudaEventCreateWithFlags(&ev_fork, cudaEventDisableTiming);
        cudaEventCreateWithFlags(&ev_scan, cudaEventDisableTiming);
        cudaEventCreateWithFlags(&ev_join, cudaEventDisableTiming);
    }

    // Identify inputs by element count (robust to metadata ordering).
    const float* x = nullptr; const void* ei = nullptr;
    const float* w1 = nullptr; const float* w2 = nullptr;
    const float* b1 = nullptr; const float* b2 = nullptr;
    long long x_sz = 0, e_sz = 0;
    for (int i = 0; i < n_in; i++) {
        long long sz = in_sizes[i];
        if (sz == 16) {
            if (!b1) b1 = (const float*)d_in[i];
            else     b2 = (const float*)d_in[i];
        } else if (sz == 256) {
            w2 = (const float*)d_in[i];
        } else if (sz == 8192) {
            w1 = (const float*)d_in[i];
        } else if (sz > 8192) {
            if (!x) { x = (const float*)d_in[i]; x_sz = sz; }
            else if (sz > x_sz) { ei = (const void*)x; e_sz = x_sz;
                                  x = (const float*)d_in[i]; x_sz = sz; }
            else { ei = (const void*)d_in[i]; e_sz = sz; }
        }
    }

    float* out = (float*)d_out;
    int n = (int)(x_sz / 512);
    int e = (int)(e_sz / 2);
    if (n > N_MAX) n = N_MAX;
    if (e > E_MAX) e = E_MAX;

    int nb = (n + 1023) / 1024;

    // fork: gemm1 (independent of graph structure) on s2
    cudaEventRecord(ev_fork, 0);
    cudaStreamWaitEvent(s2, ev_fork, 0);
    k_gemm1<<<(n + G1_NODES - 1) / G1_NODES, 128, 0, s2>>>(x, w1, n);

    // preprocessing chain on the capture (default) stream
    k_init<<<(n + 255) / 256, 256>>>((const int*)ei, e, n);
    k_count<<<(e / 2 + 255) / 256, 256>>>(ei, e, n);
    k_scan_block<<<nb, 1024>>>(n);
    k_scan_add<<<(n + 255) / 256, 256>>>(n, nb);
    cudaEventRecord(ev_scan, 0);               // dis ready

    // scale (needs gemm1 + dis) overlaps place on the main stream
    cudaStreamWaitEvent(s2, ev_scan, 0);
    k_scale<<<(n * 4 + 255) / 256, 256, 0, s2>>>(n);
    cudaEventRecord(ev_join, s2);

    k_place<<<(e / 2 + 255) / 256, 256>>>(ei, e, n);

    cudaStreamWaitEvent(0, ev_join, 0);
    k_gather1<<<(n * 8 + 255) / 256, 256>>>(b1, w2, n);
    k_gather2<<<(n * 8 + 255) / 256, 256>>>(b2, out, n);
}

// round 11
// speedup vs baseline: 1.0840x; 1.0840x over previous
#include <cuda_runtime.h>
#include <cuda_fp16.h>
#include <cstdint>

#define N_MAX 100000
#define E_MAX 3200000
#define CAP 64
#define OVF_MAX 16384

// ---------------- scratch (static device globals; no allocs) ----------------
__device__ int    d_is64;
__device__ int    d_cnt[N_MAX];
__device__ int    d_novf;
__device__ int2   d_ovf[OVF_MAX];
__device__ int    d_srcs[(size_t)N_MAX * CAP];
__device__ float  d_dis[N_MAX];
__device__ float  d_g1[(size_t)N_MAX * 16];      // fp32 gemm1 output (unscaled)
__device__ __half d_g1h[(size_t)N_MAX * 16];     // fp16 scaled layer-1 features
__device__ __half d_g2h[(size_t)N_MAX * 16];     // fp16 scaled layer-2 features
__device__ float  d_ex1[(size_t)N_MAX * 16];     // fp32 overflow extras, layer 1
__device__ float  d_ex2[(size_t)N_MAX * 16];     // fp32 overflow extras, layer 2

// ---------------- init: zero cnt/extras/novf; block 0 probes edge dtype ----------------
__global__ void k_init(const int* __restrict__ ei32, int e, int n) {
    int i = blockIdx.x * blockDim.x + threadIdx.x;
    if (i < n) {
        d_cnt[i] = 0;
        float4 z = make_float4(0.f, 0.f, 0.f, 0.f);
#pragma unroll
        for (int q = 0; q < 4; q++) {
            *(float4*)&d_ex1[(size_t)i * 16 + q * 4] = z;
            *(float4*)&d_ex2[(size_t)i * 16 + q * 4] = z;
        }
    }
    if (i == 0) d_novf = 0;
    if (blockIdx.x == 0) {
        // int64 little-endian node ids < 2^31 have zero high words at odd int32 offsets
        int total32 = 2 * e;               // in-bounds under BOTH interpretations
        int stride = (total32 / 2048) * 2; // even stride keeps parity odd
        if (stride < 2) stride = 2;
        int nz = 0;
#pragma unroll
        for (int r = 0; r < 4; r++) {
            long long p = 1 + (long long)(threadIdx.x * 4 + r) * stride;
            if (p < total32) nz += (__ldg(&ei32[p]) != 0);
        }
        int any = __syncthreads_or(nz);
        if (threadIdx.x == 0) d_is64 = any ? 0 : 1;
    }
}

__device__ __forceinline__ int load_idx(const void* ei, long long pos, int is64) {
    return is64 ? (int)((const long long*)ei)[pos] : ((const int*)ei)[pos];
}

// ---------------- place: bucket scatter (no count/scan passes) ----------------
__global__ void k_place(const void* __restrict__ ei, int e, int n) {
    int i = blockIdx.x * blockDim.x + threadIdx.x;
    if (i < e) {
        int is64 = d_is64;
        int s = load_idx(ei, i, is64);                  // src = first row
        int d = load_idx(ei, (long long)e + i, is64);   // dst = second row
        if (d >= 0 && d < n && s >= 0 && s < n) {
            int p = atomicAdd(&d_cnt[d], 1);
            if (p < CAP) d_srcs[(size_t)d * CAP + p] = s;
            else {
                int o = atomicAdd(&d_novf, 1);
                if (o < OVF_MAX) d_ovf[o] = make_int2(d, s);
            }
        }
    }
}

// ---------------- layer-1 GEMM: g1 = x @ w1, register-staged prefetch pipeline ----------------
__global__ void __launch_bounds__(128) k_gemm1(const float* __restrict__ x,
                                               const float* __restrict__ w1, int n) {
    __shared__ float xs[256][36];            // pad 36: conflict-free float4 reads
    __shared__ float ws[32 * 16];
    int tid = threadIdx.x;
    int base = blockIdx.x * 256;

    unsigned long long a0[8], a1[8];
#pragma unroll
    for (int q = 0; q < 8; q++) { a0[q] = 0ull; a1[q] = 0ull; }

    float4 xreg[16];
    float4 wreg;

#define PREFETCH_TILE(KT)                                                        \
    {                                                                            \
        wreg = ((const float4*)(w1 + (size_t)(KT) * 16))[tid];                   \
        _Pragma("unroll")                                                        \
        for (int r = 0; r < 16; r++) {                                           \
            int f4 = r * 128 + tid;                                              \
            int rown = f4 >> 3;                                                  \
            int col  = f4 & 7;                                                   \
            int gn = base + rown;                                                \
            xreg[r] = (gn < n)                                                   \
                ? *(const float4*)&x[(size_t)gn * 512 + (KT) + col * 4]          \
                : make_float4(0.f, 0.f, 0.f, 0.f);                               \
        }                                                                        \
    }

    PREFETCH_TILE(0)
    for (int kt = 0; kt < 512; kt += 32) {
        // drain staged tile to smem
        ((float4*)ws)[tid] = wreg;
#pragma unroll
        for (int r = 0; r < 16; r++) {
            int f4 = r * 128 + tid;
            int rown = f4 >> 3;
            int col  = f4 & 7;
            *(float4*)&xs[rown][col * 4] = xreg[r];
        }
        __syncthreads();
        // issue next tile's loads before compute (overlap DRAM with FMA)
        if (kt + 32 < 512) PREFETCH_TILE(kt + 32)
#pragma unroll
        for (int k4 = 0; k4 < 8; k4++) {
            float4 xa = *(const float4*)&xs[tid][k4 * 4];
            float4 xb = *(const float4*)&xs[tid + 128][k4 * 4];
#pragma unroll
            for (int kk = 0; kk < 4; kk++) {
                int k = k4 * 4 + kk;
                const ulonglong2* wp2 = (const ulonglong2*)&ws[k * 16];
                float fa = (&xa.x)[kk];
                float fb = (&xb.x)[kk];
                unsigned long long pa, pb;
                asm("mov.b64 %0, {%1, %1};" : "=l"(pa) : "f"(fa));
                asm("mov.b64 %0, {%1, %1};" : "=l"(pb) : "f"(fb));
#pragma unroll
                for (int q = 0; q < 4; q++) {
                    ulonglong2 w2v = wp2[q];
                    asm("fma.rn.f32x2 %0, %1, %2, %0;" : "+l"(a0[2 * q])     : "l"(pa), "l"(w2v.x));
                    asm("fma.rn.f32x2 %0, %1, %2, %0;" : "+l"(a0[2 * q + 1]) : "l"(pa), "l"(w2v.y));
                    asm("fma.rn.f32x2 %0, %1, %2, %0;" : "+l"(a1[2 * q])     : "l"(pb), "l"(w2v.x));
                    asm("fma.rn.f32x2 %0, %1, %2, %0;" : "+l"(a1[2 * q + 1]) : "l"(pb), "l"(w2v.y));
                }
            }
        }
        __syncthreads();
    }
#undef PREFETCH_TILE

#pragma unroll
    for (int half = 0; half < 2; half++) {
        int node = base + half * 128 + tid;
        if (node < n) {
            unsigned long long* ap = half ? a1 : a0;
            float outv[16];
#pragma unroll
            for (int q = 0; q < 8; q++) {
                float lo, hi;
                asm("mov.b64 {%0, %1}, %2;" : "=f"(lo), "=f"(hi) : "l"(ap[q]));
                outv[2 * q]     = lo;
                outv[2 * q + 1] = hi;
            }
#pragma unroll
            for (int q = 0; q < 4; q++)
                *(float4*)&d_g1[(size_t)node * 16 + q * 4] =
                    make_float4(outv[4 * q], outv[4 * q + 1], outv[4 * q + 2], outv[4 * q + 3]);
        }
    }
}

// ---------------- scale: dis = rsqrt(cnt+1); g1h = half(g1 * dis) ----------------
__global__ void k_scale(int n) {
    int t = blockIdx.x * blockDim.x + threadIdx.x;   // one float4 -> 4 halves per thread
    int node = t >> 2;
    if (node < n) {
        float di = rsqrtf((float)(__ldg(&d_cnt[node]) + 1));
        if ((t & 3) == 0) d_dis[node] = di;
        float4 v = *(const float4*)&d_g1[(size_t)t * 4];
        __half2 h01 = __floats2half2_rn(v.x * di, v.y * di);
        __half2 h23 = __floats2half2_rn(v.z * di, v.w * di);
        uint2 st;
        st.x = *(unsigned int*)&h01;
        st.y = *(unsigned int*)&h23;
        *(uint2*)&d_g1h[(size_t)t * 4] = st;
    }
}

// ---------------- overflow fixup: ex[d] += tab[s] for each overflow edge ----------------
__global__ void k_fix(const __half* __restrict__ tab, float* __restrict__ ex) {
    int i = blockIdx.x * blockDim.x + threadIdx.x;
    int m = d_novf;
    if (m > OVF_MAX) m = OVF_MAX;
    if (i < m) {
        int2 p = d_ovf[i];
        const __half* r = &tab[(size_t)p.y * 16];
        float* w = &ex[(size_t)p.x * 16];
#pragma unroll
        for (int k = 0; k < 16; k++) atomicAdd(&w[k], __half2float(r[k]));
    }
}

// ---------------- gather 1: 8 threads/node, fp16 features, fused GEMM2 ----------------
__global__ void k_gather1(const float* __restrict__ b1,
                          const float* __restrict__ w2, int n) {
    __shared__ float w2s[256];
    if (threadIdx.x < 256) w2s[threadIdx.x] = w2[threadIdx.x];
    __syncthreads();

    int t = blockIdx.x * blockDim.x + threadIdx.x;
    int node = t >> 3, c = t & 3, h = (t >> 2) & 1;
    bool act = node < n;
    int nc = act ? node : (n - 1);

    int cnt = __ldg(&d_cnt[nc]);
    int cl = cnt < CAP ? cnt : CAP;
    float di = __ldg(&d_dis[nc]);
    int novf = d_novf;
    float ax = 0.f, ay = 0.f, az = 0.f, aw = 0.f;
    if (h == 0) {
        uint2 raw = *(const uint2*)&d_g1h[(size_t)nc * 16 + c * 4];  // self-loop
        float2 lo = __half22float2(*(__half2*)&raw.x);
        float2 hi = __half22float2(*(__half2*)&raw.y);
        ax = lo.x; ay = lo.y; az = hi.x; aw = hi.y;
        if (novf) {
            float4 ex = *(const float4*)&d_ex1[(size_t)nc * 16 + c * 4];
            ax += ex.x; ay += ex.y; az += ex.z; aw += ex.w;
        }
    }
    const int* bp = &d_srcs[(size_t)nc * CAP];
#pragma unroll 4
    for (int j = h; j < cl; j += 2) {
        int s = __ldg(&bp[j]);
        uint2 raw = *(const uint2*)&d_g1h[(size_t)s * 16 + c * 4];
        float2 lo = __half22float2(*(__half2*)&raw.x);
        float2 hi = __half22float2(*(__half2*)&raw.y);
        ax += lo.x; ay += lo.y; az += hi.x; aw += hi.y;
    }
    ax += __shfl_xor_sync(0xffffffffu, ax, 4);
    ay += __shfl_xor_sync(0xffffffffu, ay, 4);
    az += __shfl_xor_sync(0xffffffffu, az, 4);
    aw += __shfl_xor_sync(0xffffffffu, aw, 4);

    float4 b4 = *(const float4*)&b1[c * 4];
    float al[4];
    al[0] = fmaxf(fmaf(ax, di, b4.x), 0.f);
    al[1] = fmaxf(fmaf(ay, di, b4.y), 0.f);
    al[2] = fmaxf(fmaf(az, di, b4.z), 0.f);
    al[3] = fmaxf(fmaf(aw, di, b4.w), 0.f);

    int lane = threadIdx.x & 31;
    int lb = lane & ~3;
    float h2[4] = {0.f, 0.f, 0.f, 0.f};
#pragma unroll
    for (int j = 0; j < 16; j++) {
        float aj = __shfl_sync(0xffffffffu, al[j & 3], lb + (j >> 2));
#pragma unroll
        for (int q = 0; q < 4; q++)
            h2[q] = fmaf(aj, w2s[j * 16 + c * 4 + q], h2[q]);
    }
    if (act && h == 0) {
        __half2 o01 = __floats2half2_rn(h2[0] * di, h2[1] * di);
        __half2 o23 = __floats2half2_rn(h2[2] * di, h2[3] * di);
        uint2 st;
        st.x = *(unsigned int*)&o01;
        st.y = *(unsigned int*)&o23;
        *(uint2*)&d_g2h[(size_t)node * 16 + c * 4] = st;
    }
}

// ---------------- gather 2: 8 threads/node, logits + log_softmax ----------------
__global__ void k_gather2(const float* __restrict__ b2, float* __restrict__ out, int n) {
    int t = blockIdx.x * blockDim.x + threadIdx.x;
    int node = t >> 3, c = t & 3, h = (t >> 2) & 1;
    bool act = node < n;
    int nc = act ? node : (n - 1);

    int cnt = __ldg(&d_cnt[nc]);
    int cl = cnt < CAP ? cnt : CAP;
    float di = __ldg(&d_dis[nc]);
    int novf = d_novf;
    float ax = 0.f, ay = 0.f, az = 0.f, aw = 0.f;
    if (h == 0) {
        uint2 raw = *(const uint2*)&d_g2h[(size_t)nc * 16 + c * 4];  // self-loop
        float2 lo = __half22float2(*(__half2*)&raw.x);
        float2 hi = __half22float2(*(__half2*)&raw.y);
        ax = lo.x; ay = lo.y; az = hi.x; aw = hi.y;
        if (novf) {
            float4 ex = *(const float4*)&d_ex2[(size_t)nc * 16 + c * 4];
            ax += ex.x; ay += ex.y; az += ex.z; aw += ex.w;
        }
    }
    const int* bp = &d_srcs[(size_t)nc * CAP];
#pragma unroll 4
    for (int j = h; j < cl; j += 2) {
        int s = __ldg(&bp[j]);
        uint2 raw = *(const uint2*)&d_g2h[(size_t)s * 16 + c * 4];
        float2 lo = __half22float2(*(__half2*)&raw.x);
        float2 hi = __half22float2(*(__half2*)&raw.y);
        ax += lo.x; ay += lo.y; az += hi.x; aw += hi.y;
    }
    ax += __shfl_xor_sync(0xffffffffu, ax, 4);
    ay += __shfl_xor_sync(0xffffffffu, ay, 4);
    az += __shfl_xor_sync(0xffffffffu, az, 4);
    aw += __shfl_xor_sync(0xffffffffu, aw, 4);

    float4 b4 = *(const float4*)&b2[c * 4];
    float l0 = fmaf(ax, di, b4.x);
    float l1 = fmaf(ay, di, b4.y);
    float l2 = fmaf(az, di, b4.z);
    float l3 = fmaf(aw, di, b4.w);

    float m = fmaxf(fmaxf(l0, l1), fmaxf(l2, l3));
    m = fmaxf(m, __shfl_xor_sync(0xffffffffu, m, 1));
    m = fmaxf(m, __shfl_xor_sync(0xffffffffu, m, 2));
    float s4 = expf(l0 - m) + expf(l1 - m) + expf(l2 - m) + expf(l3 - m);
    s4 += __shfl_xor_sync(0xffffffffu, s4, 1);
    s4 += __shfl_xor_sync(0xffffffffu, s4, 2);
    float lse = m + logf(s4);

    if (act && h == 0)
        *(float4*)&out[(size_t)node * 16 + c * 4] =
            make_float4(l0 - lse, l1 - lse, l2 - lse, l3 - lse);
}

// ---------------- launch (fork: gemm1 parallel with init+place) ----------------
extern "C" void kernel_launch(void* const* d_in, const int* in_sizes, int n_in,
                              void* d_out, int out_size) {
    static cudaStream_t s2 = nullptr;
    static cudaEvent_t ev_fork = nullptr, ev_g = nullptr;
    if (s2 == nullptr) {
        cudaStreamCreateWithFlags(&s2, cudaStreamNonBlocking);
        cudaEventCreateWithFlags(&ev_fork, cudaEventDisableTiming);
        cudaEventCreateWithFlags(&ev_g, cudaEventDisableTiming);
    }

    // Identify inputs by element count (robust to metadata ordering).
    const float* x = nullptr; const void* ei = nullptr;
    const float* w1 = nullptr; const float* w2 = nullptr;
    const float* b1 = nullptr; const float* b2 = nullptr;
    long long x_sz = 0, e_sz = 0;
    for (int i = 0; i < n_in; i++) {
        long long sz = in_sizes[i];
        if (sz == 16) {
            if (!b1) b1 = (const float*)d_in[i];
            else     b2 = (const float*)d_in[i];
        } else if (sz == 256) {
            w2 = (const float*)d_in[i];
        } else if (sz == 8192) {
            w1 = (const float*)d_in[i];
        } else if (sz > 8192) {
            if (!x) { x = (const float*)d_in[i]; x_sz = sz; }
            else if (sz > x_sz) { ei = (const void*)x; e_sz = x_sz;
                                  x = (const float*)d_in[i]; x_sz = sz; }
            else { ei = (const void*)d_in[i]; e_sz = sz; }
        }
    }

    float* out = (float*)d_out;
    int n = (int)(x_sz / 512);
    int e = (int)(e_sz / 2);
    if (n > N_MAX) n = N_MAX;
    if (e > E_MAX) e = E_MAX;

    // fork: gemm1 (independent of graph structure) on s2
    cudaEventRecord(ev_fork, 0);
    cudaStreamWaitEvent(s2, ev_fork, 0);
    k_gemm1<<<(n + 255) / 256, 128, 0, s2>>>(x, w1, n);
    cudaEventRecord(ev_g, s2);

    // preprocessing on the capture (default) stream
    k_init<<<(n + 255) / 256, 256>>>((const int*)ei, e, n);
    k_place<<<(e + 255) / 256, 256>>>(ei, e, n);

    // join: scale needs gemm1 output + cnt
    cudaStreamWaitEvent(0, ev_g, 0);
    k_scale<<<(n * 4 + 255) / 256, 256>>>(n);
    k_fix<<<OVF_MAX / 256, 256>>>(d_g1h, d_ex1);
    k_gather1<<<(n * 8 + 255) / 256, 256>>>(b1, w2, n);
    k_fix<<<OVF_MAX / 256, 256>>>(d_g2h, d_ex2);
    k_gather2<<<(n * 8 + 255) / 256, 256>>>(b2, out, n);
}